// round 9
// baseline (speedup 1.0000x reference)
#include <cuda_runtime.h>
#include <cuda_fp16.h>
#include <cstdint>
#include <math.h>

#define N_NODES_MAX 100000
#define E_MAX       1600000
#define D1 64
#define D2 32
#define SCAN_B 512
#define NB_MAX 256
#define L1_NODES 64
#define IN_STRIDE 72   // floats; 288B = multiple of 16B

// Scratch (no allocations allowed)
__device__ __half g_xh  [(size_t)N_NODES_MAX * D1];
__device__ __half g_x2th[(size_t)N_NODES_MAX * D2];
__device__ int    g_cnt [N_NODES_MAX];   // zeroed by scan (self-restoring)
__device__ int    g_row [N_NODES_MAX + 1];
__device__ int    g_cur [N_NODES_MAX];
__device__ int    g_csr [E_MAX];
__device__ int    g_agg [NB_MAX];        // lookback publish slots (0 = empty)

// ---------------------------------------------------------------------------
__device__ __forceinline__ void unpack2(unsigned long long v, float& lo, float& hi) {
    unsigned int a, b;
    asm("mov.b64 {%0, %1}, %2;" : "=r"(a), "=r"(b) : "l"(v));
    lo = __uint_as_float(a);
    hi = __uint_as_float(b);
}
__device__ __forceinline__ unsigned long long fma2(unsigned long long a,
                                                   unsigned long long b,
                                                   unsigned long long c) {
    unsigned long long d;
    asm("fma.rn.f32x2 %0, %1, %2, %3;" : "=l"(d) : "l"(a), "l"(b), "l"(c));
    return d;
}

// ---------------------------------------------------------------------------
// conv (fp32->fp16) + degree histogram merged. cnt zeroed by previous scan.
__global__ void conv_hist_kernel(const float4* __restrict__ x4,
                                 uint2* __restrict__ xh,
                                 const int* __restrict__ dst,
                                 int* __restrict__ cnt,
                                 int n4, int E) {
    int i = blockIdx.x * blockDim.x + threadIdx.x;
    if (i < n4) {
        float4 v = x4[i];
        __half2 a = __floats2half2_rn(v.x, v.y);
        __half2 b = __floats2half2_rn(v.z, v.w);
        uint2 o;
        o.x = *reinterpret_cast<unsigned int*>(&a);
        o.y = *reinterpret_cast<unsigned int*>(&b);
        xh[i] = o;
    }
    if (i < E) atomicAdd(&cnt[dst[i]], 1);
}

// ---------------------------------------------------------------------------
// Single-pass exclusive scan, decoupled lookback (all blocks co-resident).
// Zeroes cnt for the next replay.
__global__ void __launch_bounds__(SCAN_B)
scan_kernel(int* __restrict__ cnt, int* __restrict__ row, int* __restrict__ cur,
            int* __restrict__ agg, int N, int E) {
    __shared__ int s[SCAN_B];
    int t = threadIdx.x;
    int b = blockIdx.x;
    int i = b * SCAN_B + t;
    int v = (i < N) ? cnt[i] : 0;
    if (i < N) cnt[i] = 0;
    s[t] = v;
    __syncthreads();
#pragma unroll
    for (int off = 1; off < SCAN_B; off <<= 1) {
        int u = 0;
        if (t >= off) u = s[t - off];
        __syncthreads();
        if (t >= off) s[t] += u;
        __syncthreads();
    }
    int incl = s[t];
    if (t == 0) atomicExch(&agg[b], s[SCAN_B - 1] + 1);

    int acc = 0;
    for (int idx = t; idx < b; idx += SCAN_B) {
        volatile int* p = &agg[idx];
        int a;
        while ((a = *p) == 0) { }
        acc += a - 1;
    }
    __syncthreads();
    s[t] = acc;
    __syncthreads();
#pragma unroll
    for (int off = SCAN_B / 2; off > 0; off >>= 1) {
        if (t < off) s[t] += s[t + off];
        __syncthreads();
    }
    int offset = s[0];
    if (i < N) {
        int r = offset + incl - v;
        row[i] = r;
        cur[i] = r;
    }
    if (i == N) row[N] = E;
}

// ---------------------------------------------------------------------------
__global__ void fill_kernel(const int* __restrict__ src, const int* __restrict__ dst,
                            int* __restrict__ cur, int* __restrict__ csr,
                            int* __restrict__ agg, int E) {
    int i = blockIdx.x * blockDim.x + threadIdx.x;
    if (i < NB_MAX) agg[i] = 0;
    if (i < E) {
        int d = dst[i];
        int p = atomicAdd(&cur[d], 1);
        csr[p] = src[i];
    }
}

// ---------------------------------------------------------------------------
__device__ __forceinline__ void acc_h8(float* acc, uint4 v) {
    float2 f;
    f = __half22float2(*reinterpret_cast<__half2*>(&v.x)); acc[0] += f.x; acc[1] += f.y;
    f = __half22float2(*reinterpret_cast<__half2*>(&v.y)); acc[2] += f.x; acc[3] += f.y;
    f = __half22float2(*reinterpret_cast<__half2*>(&v.z)); acc[4] += f.x; acc[5] += f.y;
    f = __half22float2(*reinterpret_cast<__half2*>(&v.w)); acc[6] += f.x; acc[7] += f.y;
}

// ---------------------------------------------------------------------------
// Fused layer 1 + W2 pre-transform. Block = 256 threads, 64 nodes.
//   Phase A: fp16 gather mean (8 lanes/node, 2 node-halves per thread).
//   Phase B: x1 = relu(agg@W1+b1). Tile = 4 nodes x 4 outputs. FFMA2 packs
//            K-PAIRS: acc_j += (x_k,x_{k+1}) * (W[k][j],W[k+1][j]);
//            x pair = direct LDS.64, W pairs pre-packed k-pair-major in smem.
//   Phase C: x2t = x1@W2 (fp16 store). Tile = 4 nodes x 2 outputs, same trick.
__global__ void __launch_bounds__(256, 4)
layer1_kernel(const __half* __restrict__ xh,
              const int*    __restrict__ csr,
              const int*    __restrict__ row,
              const float*  __restrict__ W1,   // [64,64] (k, j)
              const float*  __restrict__ b1,   // [64]
              const float*  __restrict__ W2,   // [64,32] (k, j)
              __half*       __restrict__ x2th, // [N,32] fp16
              int N) {
    __shared__ float Wp1[(D1 / 2) * D1 * 2];   // [kp][j][2]: (W[2kp][j], W[2kp+1][j])
    __shared__ float Wp2[(D1 / 2) * D2 * 2];
    __shared__ float b1s[D1];
    __shared__ float in_s[L1_NODES][IN_STRIDE];

    for (int i = threadIdx.x; i < D1 * D1; i += 256) {
        int k = i >> 6, j = i & 63;
        Wp1[(k >> 1) * (D1 * 2) + j * 2 + (k & 1)] = W1[i];
    }
    for (int i = threadIdx.x; i < D1 * D2; i += 256) {
        int k = i >> 5, j = i & 31;
        Wp2[(k >> 1) * (D2 * 2) + j * 2 + (k & 1)] = W2[i];
    }
    if (threadIdx.x < D1) b1s[threadIdx.x] = b1[threadIdx.x];
    __syncthreads();

    // ---- Phase A: fp16 gather, 2 node-halves ----
    {
        int lane = threadIdx.x & 7;
        int nlb = threadIdx.x >> 3;   // 0..31
        const uint4* xh4 = reinterpret_cast<const uint4*>(xh);  // row stride 8
#pragma unroll
        for (int half = 0; half < 2; half++) {
            int nl = nlb + half * 32;
            int node = blockIdx.x * L1_NODES + nl;
            if (node >= N) node = N - 1;
            int beg = row[node], end = row[node + 1];

            float acc[8];
#pragma unroll
            for (int i = 0; i < 8; i++) acc[i] = 0.f;

            int e = beg;
            for (; e + 3 < end; e += 4) {
                int s0 = csr[e], s1 = csr[e + 1], s2 = csr[e + 2], s3 = csr[e + 3];
                uint4 v0 = xh4[(size_t)s0 * 8 + lane];
                uint4 v1 = xh4[(size_t)s1 * 8 + lane];
                uint4 v2 = xh4[(size_t)s2 * 8 + lane];
                uint4 v3 = xh4[(size_t)s3 * 8 + lane];
                acc_h8(acc, v0); acc_h8(acc, v1); acc_h8(acc, v2); acc_h8(acc, v3);
            }
            for (; e < end; e++) {
                uint4 v0 = xh4[(size_t)csr[e] * 8 + lane];
                acc_h8(acc, v0);
            }
            float inv = 1.0f / fmaxf((float)(end - beg), 1.0f);
            float4 r0 = make_float4(acc[0] * inv, acc[1] * inv, acc[2] * inv, acc[3] * inv);
            float4 r1 = make_float4(acc[4] * inv, acc[5] * inv, acc[6] * inv, acc[7] * inv);
            float4* rp = reinterpret_cast<float4*>(&in_s[nl][0]);
            rp[lane * 2]     = r0;
            rp[lane * 2 + 1] = r1;
        }
    }
    __syncthreads();

    int jg = threadIdx.x & 15;    // output group
    int ng = threadIdx.x >> 4;    // node group 0..15
    int j  = jg * 4;
    int nb0 = ng * 4;

    // ---- Phase B: x1 = relu(agg @ W1 + b1), k-pair FFMA2 ----
    unsigned long long acc[4][4];
#pragma unroll
    for (int nn = 0; nn < 4; nn++)
#pragma unroll
        for (int jj = 0; jj < 4; jj++) acc[nn][jj] = 0ull;

#pragma unroll 8
    for (int kp = 0; kp < D1 / 2; kp++) {
        ulonglong2 wa = *reinterpret_cast<const ulonglong2*>(&Wp1[kp * (D1 * 2) + j * 2]);
        ulonglong2 wb = *reinterpret_cast<const ulonglong2*>(&Wp1[kp * (D1 * 2) + j * 2 + 4]);
#pragma unroll
        for (int nn = 0; nn < 4; nn++) {
            unsigned long long xv =
                *reinterpret_cast<const unsigned long long*>(&in_s[nb0 + nn][kp * 2]);
            acc[nn][0] = fma2(xv, wa.x, acc[nn][0]);
            acc[nn][1] = fma2(xv, wa.y, acc[nn][1]);
            acc[nn][2] = fma2(xv, wb.x, acc[nn][2]);
            acc[nn][3] = fma2(xv, wb.y, acc[nn][3]);
        }
    }
    float x1v[4][4];
#pragma unroll
    for (int nn = 0; nn < 4; nn++) {
#pragma unroll
        for (int jj = 0; jj < 4; jj++) {
            float lo, hi;
            unpack2(acc[nn][jj], lo, hi);
            x1v[nn][jj] = fmaxf(lo + hi + b1s[j + jj], 0.f);
        }
    }
    __syncthreads();   // all Phase-B reads of agg done
#pragma unroll
    for (int nn = 0; nn < 4; nn++)
        *reinterpret_cast<float4*>(&in_s[nb0 + nn][j]) =
            make_float4(x1v[nn][0], x1v[nn][1], x1v[nn][2], x1v[nn][3]);
    __syncthreads();   // x1 staged

    // ---- Phase C: x2t = x1 @ W2 (fp16 store), k-pair FFMA2 ----
    int j2 = jg * 2;
    unsigned long long pacc[4][2];
#pragma unroll
    for (int nn = 0; nn < 4; nn++) { pacc[nn][0] = 0ull; pacc[nn][1] = 0ull; }

#pragma unroll 8
    for (int kp = 0; kp < D1 / 2; kp++) {
        ulonglong2 w = *reinterpret_cast<const ulonglong2*>(&Wp2[kp * (D2 * 2) + j2 * 2]);
#pragma unroll
        for (int nn = 0; nn < 4; nn++) {
            unsigned long long xv =
                *reinterpret_cast<const unsigned long long*>(&in_s[nb0 + nn][kp * 2]);
            pacc[nn][0] = fma2(xv, w.x, pacc[nn][0]);
            pacc[nn][1] = fma2(xv, w.y, pacc[nn][1]);
        }
    }
#pragma unroll
    for (int nn = 0; nn < 4; nn++) {
        float l0, h0, l1, h1;
        unpack2(pacc[nn][0], l0, h0);
        unpack2(pacc[nn][1], l1, h1);
        int node = blockIdx.x * L1_NODES + nb0 + nn;
        if (node >= N) node = N - 1;
        *reinterpret_cast<__half2*>(x2th + (size_t)node * D2 + j2) =
            __floats2half2_rn(l0 + h0, l1 + h1);
    }
}

// ---------------------------------------------------------------------------
// Layer 2 + readout (fp16 gather). 8 lanes per node, 8B per lane.
__global__ void __launch_bounds__(512)
layer2_kernel(const __half* __restrict__ x2th,  // [N,32] fp16
              const int*    __restrict__ csr,
              const int*    __restrict__ row,
              const float*  __restrict__ b2,
              const float*  __restrict__ Wd,
              const float*  __restrict__ bd,
              float*        __restrict__ out,   // [N]
              int N) {
    __shared__ float bs[D2];
    if (threadIdx.x < D2) bs[threadIdx.x] = b2[threadIdx.x];
    __syncthreads();

    int grp = threadIdx.x >> 3;
    int lane = threadIdx.x & 7;
    int node = blockIdx.x * 64 + grp;
    if (node >= N) node = N - 1;

    int beg = row[node], end = row[node + 1];
    const uint2* x2 = reinterpret_cast<const uint2*>(x2th);  // row stride 8

    float a0 = 0.f, a1 = 0.f, a2 = 0.f, a3 = 0.f;
    int e = beg;
    for (; e + 3 < end; e += 4) {
        int s0 = csr[e], s1 = csr[e + 1], s2 = csr[e + 2], s3 = csr[e + 3];
        uint2 v0 = x2[(size_t)s0 * 8 + lane];
        uint2 v1 = x2[(size_t)s1 * 8 + lane];
        uint2 v2 = x2[(size_t)s2 * 8 + lane];
        uint2 v3 = x2[(size_t)s3 * 8 + lane];
        float2 f;
        f = __half22float2(*reinterpret_cast<__half2*>(&v0.x)); a0 += f.x; a1 += f.y;
        f = __half22float2(*reinterpret_cast<__half2*>(&v0.y)); a2 += f.x; a3 += f.y;
        f = __half22float2(*reinterpret_cast<__half2*>(&v1.x)); a0 += f.x; a1 += f.y;
        f = __half22float2(*reinterpret_cast<__half2*>(&v1.y)); a2 += f.x; a3 += f.y;
        f = __half22float2(*reinterpret_cast<__half2*>(&v2.x)); a0 += f.x; a1 += f.y;
        f = __half22float2(*reinterpret_cast<__half2*>(&v2.y)); a2 += f.x; a3 += f.y;
        f = __half22float2(*reinterpret_cast<__half2*>(&v3.x)); a0 += f.x; a1 += f.y;
        f = __half22float2(*reinterpret_cast<__half2*>(&v3.y)); a2 += f.x; a3 += f.y;
    }
    for (; e < end; e++) {
        uint2 v0 = x2[(size_t)csr[e] * 8 + lane];
        float2 f;
        f = __half22float2(*reinterpret_cast<__half2*>(&v0.x)); a0 += f.x; a1 += f.y;
        f = __half22float2(*reinterpret_cast<__half2*>(&v0.y)); a2 += f.x; a3 += f.y;
    }
    float inv = 1.0f / fmaxf((float)(end - beg), 1.0f);
    int j = lane * 4;
    float h0 = fmaxf(fmaf(a0, inv, bs[j + 0]), 0.f);
    float h1 = fmaxf(fmaf(a1, inv, bs[j + 1]), 0.f);
    float h2 = fmaxf(fmaf(a2, inv, bs[j + 2]), 0.f);
    float h3 = fmaxf(fmaf(a3, inv, bs[j + 3]), 0.f);

    float v = (h0 + h1) + (h2 + h3);
#pragma unroll
    for (int off = 4; off > 0; off >>= 1)
        v += __shfl_down_sync(0xffffffffu, v, off, 8);

    if (lane == 0) {
        float m = v * (1.0f / (float)D2);
        float z = fmaf(m, Wd[0], bd[0]);
        out[node] = 1.0f / (1.0f + expf(-z));
    }
}

// ---------------------------------------------------------------------------
extern "C" void kernel_launch(void* const* d_in, const int* in_sizes, int n_in,
                              void* d_out, int out_size) {
    const float* x   = (const float*)d_in[0];
    const int*   src = (const int*)  d_in[1];
    const int*   dst = (const int*)  d_in[2];
    const float* W1  = (const float*)d_in[3];
    const float* b1  = (const float*)d_in[4];
    const float* W2  = (const float*)d_in[5];
    const float* b2  = (const float*)d_in[6];
    const float* Wd  = (const float*)d_in[7];
    const float* bd  = (const float*)d_in[8];
    float* out = (float*)d_out;

    const int N = in_sizes[0] / D1;
    const int E = in_sizes[1];

    __half *xh, *x2th;
    int *cnt, *row, *cur, *csr, *agg;
    cudaGetSymbolAddress((void**)&xh,   g_xh);
    cudaGetSymbolAddress((void**)&x2th, g_x2th);
    cudaGetSymbolAddress((void**)&cnt,  g_cnt);
    cudaGetSymbolAddress((void**)&row,  g_row);
    cudaGetSymbolAddress((void**)&cur,  g_cur);
    cudaGetSymbolAddress((void**)&csr,  g_csr);
    cudaGetSymbolAddress((void**)&agg,  g_agg);

    const int nb = (N + SCAN_B - 1) / SCAN_B;
    const int n4 = N * (D1 / 4);
    const int big = (n4 > E) ? n4 : E;

    conv_hist_kernel<<<(big + 255) / 256, 256>>>(
        reinterpret_cast<const float4*>(x), reinterpret_cast<uint2*>(xh),
        dst, cnt, n4, E);
    scan_kernel<<<nb, SCAN_B>>>(cnt, row, cur, agg, N, E);
    fill_kernel<<<(E + 255) / 256, 256>>>(src, dst, cur, csr, agg, E);

    layer1_kernel<<<(N + L1_NODES - 1) / L1_NODES, 256>>>(xh, csr, row, W1, b1, W2, x2th, N);
    layer2_kernel<<<(N + 63) / 64, 512>>>(x2th, csr, row, b2, Wd, bd, out, N);
}